// round 5
// baseline (speedup 1.0000x reference)
#include <cuda_runtime.h>
#include <cuda_bf16.h>
#include <cstdint>

// ---------------- problem constants ----------------
constexpr int T_ = 64, N_ = 40, D_ = 4, H_ = 256, R_ = 64;
constexpr int E_ = N_ * (N_ - 1);        // 1560
constexpr int TE = T_ * E_;              // 99840
constexpr int TN = T_ * N_;              // 2560

// ---------------- scratch ----------------
__device__ float g_h1[TN * H_];
__device__ float g_nbuf[TN * H_];
__device__ float g_nsum[TN * H_];
__device__ float g_n3[TN * H_];
__device__ float g_e2[TE * H_];
__device__ float g_tmp[TE * H_];
__device__ float g_e4[TE * H_];
__device__ float g_gf[TE * H_];
__device__ float g_gr[TE * H_];
__device__ float g_hf[TE * R_];
__device__ float g_hr[TE * R_];
__device__ int   g_rlist[N_ * (N_ - 1)];

__device__ __forceinline__ float eluf(float v) { return v > 0.f ? v : expm1f(v); }
__device__ __forceinline__ float sigmf(float v) { return 1.f / (1.f + expf(-v)); }

__device__ __forceinline__ void bsplit2(float x0, float x1, uint32_t& hi, uint32_t& lo) {
    asm("cvt.rn.bf16x2.f32 %0, %1, %2;" : "=r"(hi) : "f"(x1), "f"(x0));
    __nv_bfloat162 h = *reinterpret_cast<__nv_bfloat162*>(&hi);
    float r0 = x0 - __bfloat162float(h.x);
    float r1 = x1 - __bfloat162float(h.y);
    asm("cvt.rn.bf16x2.f32 %0, %1, %2;" : "=r"(lo) : "f"(r1), "f"(r0));
}

__device__ __forceinline__ void mma_bf16(float* d, const uint32_t* a, const uint32_t* b) {
    asm volatile(
        "mma.sync.aligned.m16n8k16.row.col.f32.bf16.bf16.f32 "
        "{%0,%1,%2,%3},{%4,%5,%6,%7},{%8,%9},{%0,%1,%2,%3};"
        : "+f"(d[0]), "+f"(d[1]), "+f"(d[2]), "+f"(d[3])
        : "r"(a[0]), "r"(a[1]), "r"(a[2]), "r"(a[3]), "r"(b[0]), "r"(b[1]));
}

__device__ __forceinline__ void ldsm4(uint32_t& r0, uint32_t& r1, uint32_t& r2, uint32_t& r3,
                                      uint32_t addr) {
    asm volatile("ldmatrix.sync.aligned.m8n8.x4.shared.b16 {%0,%1,%2,%3}, [%4];"
                 : "=r"(r0), "=r"(r1), "=r"(r2), "=r"(r3) : "r"(addr));
}

__device__ __forceinline__ uint32_t smem_u32(const void* p) {
    uint32_t a;
    asm("{ .reg .u64 t; cvta.to.shared.u64 t, %1; cvt.u32.u64 %0, t; }" : "=r"(a) : "l"(p));
    return a;
}

// ---------------- mlp1 fc1 (K=4, tiny) ----------------
__global__ void mlp1_fc1(const float* __restrict__ x, const float* __restrict__ W1,
                         const float* __restrict__ b1, float* __restrict__ out) {
    int idx = blockIdx.x * blockDim.x + threadIdx.x;
    int row = idx >> 8;
    int j = idx & 255;
    const float* xr = x + row * D_;
    const float* w = W1 + j * D_;
    float v = b1[j] + xr[0] * w[0] + xr[1] * w[1] + xr[2] * w[2] + xr[3] * w[3];
    out[idx] = eluf(v);
}

// ---------------- build per-node incoming edge lists ----------------
__global__ void build_rlist(const int* __restrict__ recv) {
    int n = threadIdx.x;
    if (n >= N_) return;
    int p = 0;
    for (int e = 0; e < E_; e++)
        if (recv[e] == n) g_rlist[n * (N_ - 1) + p++] = e;
}

// ---------------- edge2node scatter-add (as gather-sum) ----------------
__global__ void edge2node(const float* __restrict__ e2, float* __restrict__ nsum) {
    int b = blockIdx.x;
    int t = b / N_;
    int n = b - t * N_;
    int c = threadIdx.x;
    const int* lst = g_rlist + n * (N_ - 1);
    float s = 0.f;
#pragma unroll 13
    for (int i = 0; i < N_ - 1; i++) {
        int e = lst[i];
        s += e2[((size_t)t * E_ + e) * H_ + c];
    }
    nsum[(size_t)b * H_ + c] = s;
}

// ------------- bf16x3 tensor-core GEMM, block 128x256, ldmatrix + double buffer -------------
// C[m, 0..255] = act( sum_k A[m,k] * W[n,k] + bias[n] (+ bias2[n]) )
// MODE 0: plain A; MODE 1: gather send|recv (Kd=512); MODE 2: send|recv|skip (Kd=768)
// 8 warps, warp tile 64x64 (2x4 over M x N). k-chunk 16 floats.
// smem row stride 48B (16 bf16 + 16B pad): ldmatrix conflict-free.
constexpr int AHI_O = 0;
constexpr int ALO_O = 6144;       // 128*48
constexpr int BHI_O = 12288;
constexpr int BLO_O = 24576;      // +256*48
constexpr int STAGE = 36864;
constexpr int GEMM_SMEM = 2 * STAGE;   // 73728

template <int MODE, int ACT, bool BIAS2>
__global__ __launch_bounds__(256) void gemm_tc(
    const float* __restrict__ A, const float* __restrict__ W,
    const float* __restrict__ bias, const float* __restrict__ bias2,
    float* __restrict__ C, int Kd,
    const int* __restrict__ send, const int* __restrict__ recv,
    const float* __restrict__ src0, const float* __restrict__ src1) {
    extern __shared__ __align__(128) char smem[];
    const uint32_t sb = smem_u32(smem);

    const int tid = threadIdx.x;
    const int bm = blockIdx.x * 128;
    const int warp = tid >> 5, lane = tid & 31;

    // ---- global load roles ----
    const int ar = tid >> 1, ahalf = tid & 1;      // A: row ar, floats [ahalf*8, +8)
    const float *ar0 = nullptr, *ar1 = nullptr, *ar2 = nullptr;
    {
        int m = bm + ar;
        if (MODE == 0) {
            ar0 = A + (size_t)m * Kd;
        } else {
            int t = m / E_;
            int e = m - t * E_;
            ar0 = src0 + ((size_t)t * N_ + send[e]) * H_;
            ar1 = src0 + ((size_t)t * N_ + recv[e]) * H_;
            if (MODE == 2) ar2 = src1 + (size_t)m * H_;
        }
    }
    const float* wrow = W + (size_t)tid * Kd;      // B: row tid, all 16 floats

    // ---- ldmatrix addressing ----
    const int mi = lane >> 3, rowin = lane & 7;
    const int rsel = (mi & 1) * 8 + rowin;
    const int kh16 = (mi >> 1) * 16;
    const int wm = (warp >> 2) * 64;               // 0 / 64
    const int wn = (warp & 3) * 64;                // 0 / 64 / 128 / 192
    const uint32_t aoff = (uint32_t)((wm + rsel) * 48 + kh16);
    const uint32_t boff = (uint32_t)((wn + rsel) * 48 + kh16);

    const uint32_t a_sts = (uint32_t)(ar * 48 + ahalf * 16);
    const uint32_t b_sts = (uint32_t)(tid * 48);

    float acc[4][8][4];
#pragma unroll
    for (int i = 0; i < 4; i++)
#pragma unroll
        for (int j = 0; j < 8; j++)
#pragma unroll
            for (int k = 0; k < 4; k++) acc[i][j][k] = 0.f;

    float4 pa0, pa1, pb0, pb1, pb2, pb3;
    auto load_g = [&](int chunk) {
        int kb = chunk * 16 + ahalf * 8;
        const float* ap;
        if (MODE == 0) {
            ap = ar0 + kb;
        } else {
            int seg = kb >> 8, off = kb & 255;
            const float* base = (seg == 0) ? ar0 : ((MODE == 2 && seg == 2) ? ar2 : ar1);
            ap = base + off;
        }
        pa0 = *(const float4*)ap;
        pa1 = *(const float4*)(ap + 4);
        const float* wp = wrow + chunk * 16;
        pb0 = *(const float4*)wp;
        pb1 = *(const float4*)(wp + 4);
        pb2 = *(const float4*)(wp + 8);
        pb3 = *(const float4*)(wp + 12);
    };
    auto store_s = [&](uint32_t stg) {
        char* s = smem + stg * STAGE;
        uint4 hi, lo;
        bsplit2(pa0.x, pa0.y, hi.x, lo.x);
        bsplit2(pa0.z, pa0.w, hi.y, lo.y);
        bsplit2(pa1.x, pa1.y, hi.z, lo.z);
        bsplit2(pa1.z, pa1.w, hi.w, lo.w);
        *(uint4*)(s + AHI_O + a_sts) = hi;
        *(uint4*)(s + ALO_O + a_sts) = lo;
        bsplit2(pb0.x, pb0.y, hi.x, lo.x);
        bsplit2(pb0.z, pb0.w, hi.y, lo.y);
        bsplit2(pb1.x, pb1.y, hi.z, lo.z);
        bsplit2(pb1.z, pb1.w, hi.w, lo.w);
        *(uint4*)(s + BHI_O + b_sts) = hi;
        *(uint4*)(s + BLO_O + b_sts) = lo;
        bsplit2(pb2.x, pb2.y, hi.x, lo.x);
        bsplit2(pb2.z, pb2.w, hi.y, lo.y);
        bsplit2(pb3.x, pb3.y, hi.z, lo.z);
        bsplit2(pb3.z, pb3.w, hi.w, lo.w);
        *(uint4*)(s + BHI_O + b_sts + 16) = hi;
        *(uint4*)(s + BLO_O + b_sts + 16) = lo;
    };

    const int nchunks = Kd >> 4;
    load_g(0);
    store_s(0);
    __syncthreads();

    int cur = 0;
    for (int chunk = 0; chunk < nchunks; chunk++) {
        bool more = (chunk + 1 < nchunks);
        if (more) load_g(chunk + 1);

        const uint32_t st = sb + cur * STAGE;
        // A fragments (all 4 m16 tiles, hi+lo)
        uint32_t ah[4][4], al[4][4];
#pragma unroll
        for (int mf = 0; mf < 4; mf++) {
            uint32_t ad = st + AHI_O + aoff + mf * (16 * 48);
            ldsm4(ah[mf][0], ah[mf][1], ah[mf][2], ah[mf][3], ad);
            ldsm4(al[mf][0], al[mf][1], al[mf][2], al[mf][3], ad + (ALO_O - AHI_O));
        }
        // B tiles: 4 x n16, processed in sequence to bound live registers
#pragma unroll
        for (int bt = 0; bt < 4; bt++) {
            uint32_t bh[4], bl[4];
            uint32_t bd = st + BHI_O + boff + bt * (16 * 48);
            ldsm4(bh[0], bh[1], bh[2], bh[3], bd);
            ldsm4(bl[0], bl[1], bl[2], bl[3], bd + (BLO_O - BHI_O));
#pragma unroll
            for (int s = 0; s < 2; s++) {
                uint32_t bhp[2] = {bh[s], bh[s + 2]};
                uint32_t blp[2] = {bl[s], bl[s + 2]};
#pragma unroll
                for (int mf = 0; mf < 4; mf++) {
                    float* ac = acc[mf][bt * 2 + s];
                    mma_bf16(ac, ah[mf], bhp);   // hi*hi
                    mma_bf16(ac, ah[mf], blp);   // hi*lo
                    mma_bf16(ac, al[mf], bhp);   // lo*hi
                }
            }
        }

        if (more) store_s(cur ^ 1);
        __syncthreads();
        cur ^= 1;
    }

    // ---- epilogue ----
    const int grp = lane >> 2, q = lane & 3;
#pragma unroll
    for (int mf = 0; mf < 4; mf++) {
        int r0 = bm + wm + mf * 16 + grp;
        int r1 = r0 + 8;
#pragma unroll
        for (int j8 = 0; j8 < 8; j8++) {
            int col = wn + j8 * 8 + q * 2;
            float b0 = bias[col] + (BIAS2 ? bias2[col] : 0.f);
            float b1 = bias[col + 1] + (BIAS2 ? bias2[col + 1] : 0.f);
            float x0 = acc[mf][j8][0] + b0;
            float x1 = acc[mf][j8][1] + b1;
            float x2 = acc[mf][j8][2] + b0;
            float x3 = acc[mf][j8][3] + b1;
            if (ACT == 1) { x0 = eluf(x0); x1 = eluf(x1); x2 = eluf(x2); x3 = eluf(x3); }
            *(float2*)(C + (size_t)r0 * 256 + col) = make_float2(x0, x1);
            *(float2*)(C + (size_t)r1 * 256 + col) = make_float2(x2, x3);
        }
    }
}

// ---------------- fused bidirectional LSTM (recurrence only) ----------------
constexpr int LSTM_GROUPS = E_ / 8;
constexpr int LSTM_SMEM = 64 * 256 * 4 + 64 * 8 * 4;

__global__ __launch_bounds__(64) void lstm_kernel(
    const float* __restrict__ gf, const float* __restrict__ gr,
    const float* __restrict__ fWhh, const float* __restrict__ rWhh,
    float* __restrict__ hfOut, float* __restrict__ hrOut) {
    extern __shared__ float sm[];
    float* Wq = sm;
    float4* hsm4 = (float4*)(sm + 64 * 256);

    int dir; int grp;
    const float* gates; const float* Whh; float* hout;
    if (blockIdx.x < LSTM_GROUPS) {
        dir = 0; grp = blockIdx.x; gates = gf; Whh = fWhh; hout = hfOut;
    } else {
        dir = 1; grp = blockIdx.x - LSTM_GROUPS; gates = gr; Whh = rWhh; hout = hrOut;
    }
    const int j = threadIdx.x;

    for (int idx = j; idx < 64 * 256; idx += 64) {
        int k = idx >> 8;
        int rem = idx & 255;
        int jj = rem >> 2;
        int q = rem & 3;
        Wq[idx] = Whh[(q * 64 + jj) * 64 + k];
    }
    for (int i = j; i < 128; i += 64) hsm4[i] = make_float4(0.f, 0.f, 0.f, 0.f);

    const int e0 = grp * 8;
    float c[8];
#pragma unroll
    for (int e = 0; e < 8; e++) c[e] = 0.f;
    __syncthreads();

    for (int s = 0; s < T_; s++) {
        int t = dir ? (T_ - 1 - s) : s;
        float a0[8], a1[8], a2[8], a3[8];
#pragma unroll
        for (int e = 0; e < 8; e++) {
            const float* gp = gates + ((size_t)t * E_ + e0 + e) * 256;
            a0[e] = gp[j]; a1[e] = gp[64 + j]; a2[e] = gp[128 + j]; a3[e] = gp[192 + j];
        }
#pragma unroll 16
        for (int k = 0; k < 64; k++) {
            float4 w  = *(const float4*)&Wq[k * 256 + j * 4];
            float4 hA = hsm4[k * 2 + 0];
            float4 hB = hsm4[k * 2 + 1];
            float hv[8] = {hA.x, hA.y, hA.z, hA.w, hB.x, hB.y, hB.z, hB.w};
#pragma unroll
            for (int e = 0; e < 8; e++) {
                a0[e] = fmaf(hv[e], w.x, a0[e]);
                a1[e] = fmaf(hv[e], w.y, a1[e]);
                a2[e] = fmaf(hv[e], w.z, a2[e]);
                a3[e] = fmaf(hv[e], w.w, a3[e]);
            }
        }
        __syncthreads();
        float hn[8];
#pragma unroll
        for (int e = 0; e < 8; e++) {
            float iv = sigmf(a0[e]);
            float fv = sigmf(a1[e]);
            float gv = tanhf(a2[e]);
            float ov = sigmf(a3[e]);
            c[e] = fv * c[e] + iv * gv;
            hn[e] = ov * tanhf(c[e]);
        }
        hsm4[j * 2 + 0] = make_float4(hn[0], hn[1], hn[2], hn[3]);
        hsm4[j * 2 + 1] = make_float4(hn[4], hn[5], hn[6], hn[7]);
#pragma unroll
        for (int e = 0; e < 8; e++)
            hout[((size_t)t * E_ + e0 + e) * 64 + j] = hn[e];
        __syncthreads();
    }
}

// ---------------- output projection ----------------
__global__ void out_proj(const float* __restrict__ hf, const float* __restrict__ hr,
                         const float* __restrict__ priW, const float* __restrict__ prib,
                         const float* __restrict__ encW, const float* __restrict__ encb,
                         float* __restrict__ out) {
    int m = blockIdx.x * blockDim.x + threadIdx.x;
    if (m >= TE) return;
    const float* f = hf + (size_t)m * 64;
    const float* r = hr + (size_t)m * 64;
    float p0 = prib[0], p1 = prib[1], e0 = encb[0], e1 = encb[1];
#pragma unroll 8
    for (int k = 0; k < 64; k++) {
        float fv = f[k];
        p0 = fmaf(fv, priW[k], p0);
        p1 = fmaf(fv, priW[64 + k], p1);
        e0 = fmaf(fv, encW[k], e0);
        e1 = fmaf(fv, encW[128 + k], e1);
    }
#pragma unroll 8
    for (int k = 0; k < 64; k++) {
        float rv = r[k];
        e0 = fmaf(rv, encW[64 + k], e0);
        e1 = fmaf(rv, encW[192 + k], e1);
    }
    float4 o = make_float4(p0, p1, e0, e1);
    *(float4*)(out + (size_t)m * 4) = o;
}

// ---------------- host launch ----------------
extern "C" void kernel_launch(void* const* d_in, const int* in_sizes, int n_in,
                              void* d_out, int out_size) {
    const float* x     = (const float*)d_in[0];
    const int* send    = (const int*)d_in[2];
    const int* recv    = (const int*)d_in[3];
    const float* m1W1 = (const float*)d_in[4],  *m1b1 = (const float*)d_in[5];
    const float* m1W2 = (const float*)d_in[6],  *m1b2 = (const float*)d_in[7];
    const float* m2W1 = (const float*)d_in[8],  *m2b1 = (const float*)d_in[9];
    const float* m2W2 = (const float*)d_in[10], *m2b2 = (const float*)d_in[11];
    const float* m3W1 = (const float*)d_in[12], *m3b1 = (const float*)d_in[13];
    const float* m3W2 = (const float*)d_in[14], *m3b2 = (const float*)d_in[15];
    const float* m4W1 = (const float*)d_in[16], *m4b1 = (const float*)d_in[17];
    const float* m4W2 = (const float*)d_in[18], *m4b2 = (const float*)d_in[19];
    const float* fWih = (const float*)d_in[20], *fWhh = (const float*)d_in[21];
    const float* fbih = (const float*)d_in[22], *fbhh = (const float*)d_in[23];
    const float* rWih = (const float*)d_in[24], *rWhh = (const float*)d_in[25];
    const float* rbih = (const float*)d_in[26], *rbhh = (const float*)d_in[27];
    const float* encW = (const float*)d_in[28], *encb = (const float*)d_in[29];
    const float* priW = (const float*)d_in[30], *prib = (const float*)d_in[31];

    float *d_h1, *d_nbuf, *d_nsum, *d_n3, *d_e2, *d_tmp, *d_e4, *d_gf, *d_gr, *d_hf, *d_hr;
    cudaGetSymbolAddress((void**)&d_h1,   g_h1);
    cudaGetSymbolAddress((void**)&d_nbuf, g_nbuf);
    cudaGetSymbolAddress((void**)&d_nsum, g_nsum);
    cudaGetSymbolAddress((void**)&d_n3,   g_n3);
    cudaGetSymbolAddress((void**)&d_e2,   g_e2);
    cudaGetSymbolAddress((void**)&d_tmp,  g_tmp);
    cudaGetSymbolAddress((void**)&d_e4,   g_e4);
    cudaGetSymbolAddress((void**)&d_gf,   g_gf);
    cudaGetSymbolAddress((void**)&d_gr,   g_gr);
    cudaGetSymbolAddress((void**)&d_hf,   g_hf);
    cudaGetSymbolAddress((void**)&d_hr,   g_hr);

    cudaFuncSetAttribute(lstm_kernel, cudaFuncAttributeMaxDynamicSharedMemorySize, LSTM_SMEM);
    cudaFuncSetAttribute(gemm_tc<0, 1, false>, cudaFuncAttributeMaxDynamicSharedMemorySize, GEMM_SMEM);
    cudaFuncSetAttribute(gemm_tc<1, 1, false>, cudaFuncAttributeMaxDynamicSharedMemorySize, GEMM_SMEM);
    cudaFuncSetAttribute(gemm_tc<2, 1, false>, cudaFuncAttributeMaxDynamicSharedMemorySize, GEMM_SMEM);
    cudaFuncSetAttribute(gemm_tc<0, 0, true>,  cudaFuncAttributeMaxDynamicSharedMemorySize, GEMM_SMEM);

    build_rlist<<<1, 64>>>(recv);

    // mlp1
    mlp1_fc1<<<TN * H_ / 256, 256>>>(x, m1W1, m1b1, d_nbuf);
    gemm_tc<0, 1, false><<<TN / 128, 256, GEMM_SMEM>>>(d_nbuf, m1W2, m1b2, nullptr, d_h1,
                                                       H_, nullptr, nullptr, nullptr, nullptr);
    // mlp2 (fused node2edge gather)
    gemm_tc<1, 1, false><<<TE / 128, 256, GEMM_SMEM>>>(nullptr, m2W1, m2b1, nullptr, d_tmp,
                                                       2 * H_, send, recv, d_h1, nullptr);
    gemm_tc<0, 1, false><<<TE / 128, 256, GEMM_SMEM>>>(d_tmp, m2W2, m2b2, nullptr, d_e2,
                                                       H_, nullptr, nullptr, nullptr, nullptr);
    // edge2node + mlp3
    edge2node<<<TN, 256>>>(d_e2, d_nsum);
    gemm_tc<0, 1, false><<<TN / 128, 256, GEMM_SMEM>>>(d_nsum, m3W1, m3b1, nullptr, d_nbuf,
                                                       H_, nullptr, nullptr, nullptr, nullptr);
    gemm_tc<0, 1, false><<<TN / 128, 256, GEMM_SMEM>>>(d_nbuf, m3W2, m3b2, nullptr, d_n3,
                                                       H_, nullptr, nullptr, nullptr, nullptr);
    // mlp4 (fused gather: n[send], n[recv], skip)
    gemm_tc<2, 1, false><<<TE / 128, 256, GEMM_SMEM>>>(nullptr, m4W1, m4b1, nullptr, d_tmp,
                                                       3 * H_, send, recv, d_n3, d_e2);
    gemm_tc<0, 1, false><<<TE / 128, 256, GEMM_SMEM>>>(d_tmp, m4W2, m4b2, nullptr, d_e4,
                                                       H_, nullptr, nullptr, nullptr, nullptr);
    // LSTM input projections
    gemm_tc<0, 0, true><<<TE / 128, 256, GEMM_SMEM>>>(d_e4, fWih, fbih, fbhh, d_gf,
                                                      H_, nullptr, nullptr, nullptr, nullptr);
    gemm_tc<0, 0, true><<<TE / 128, 256, GEMM_SMEM>>>(d_e4, rWih, rbih, rbhh, d_gr,
                                                      H_, nullptr, nullptr, nullptr, nullptr);
    // recurrence
    lstm_kernel<<<2 * LSTM_GROUPS, 64, LSTM_SMEM>>>(d_gf, d_gr, fWhh, rWhh, d_hf, d_hr);
    // outputs
    out_proj<<<TE / 256, 256>>>(d_hf, d_hr, priW, prib, encW, encb, (float*)d_out);
}